// round 4
// baseline (speedup 1.0000x reference)
#include <cuda_runtime.h>
#include <stdint.h>

// atom_eng[c] = FACTOR * sum_{edges e} edge_eng[e] * scales[sp[c], sp[nbr]]
// E = 6.4M, N = 100K. Species packed to nibbles in SMEM; 2x unrolled main loop
// to double outstanding loads (latency-bound per R3 ncu: issue=11.8%, L2=48%).

#define FACTOR 0.125f  // 1/sqrt(64)

__device__ uint32_t g_packed_species[32768];  // up to 262144 nodes

__global__ void prep_kernel(const int* __restrict__ species,
                            float* __restrict__ out,
                            int N, int nwords) {
    int i = blockIdx.x * blockDim.x + threadIdx.x;
    if (i < N) out[i] = 0.0f;
    if (i < nwords) {
        uint32_t w = 0;
        int base = i << 3;
        #pragma unroll
        for (int k = 0; k < 8; k++) {
            int idx = base + k;
            if (idx < N) w |= ((uint32_t)species[idx] & 0xFu) << (k << 2);
        }
        g_packed_species[i] = w;
    }
}

__device__ __forceinline__ float4 ldcs_f4(const float4* p) {
    return __ldcs(p);
}
__device__ __forceinline__ int4 ldcs_i4(const int4* p) {
    return __ldcs(p);
}

__global__ __launch_bounds__(512) void edge_energy_sum_kernel(
    const float* __restrict__ edge_eng,     // [E]
    const float* __restrict__ scales,       // [256]
    const int*   __restrict__ ei_center,    // [E]
    const int*   __restrict__ ei_neighbor,  // [E]
    float* __restrict__ out,                // [N]
    int E, int nwords)
{
    extern __shared__ uint32_t smem[];
    float*    s_scale = (float*)smem;   // 256 floats
    uint32_t* s_pack  = smem + 256;     // nwords words

    if (threadIdx.x < 256) s_scale[threadIdx.x] = scales[threadIdx.x] * FACTOR;
    for (int i = threadIdx.x; i < nwords; i += blockDim.x)
        s_pack[i] = g_packed_species[i];
    __syncthreads();

    int nvec = E >> 2;
    int tid = blockIdx.x * blockDim.x + threadIdx.x;
    int stride = gridDim.x * blockDim.x;

    const float4* eng4 = (const float4*)edge_eng;
    const int4*   c4   = (const int4*)ei_center;
    const int4*   n4   = (const int4*)ei_neighbor;

    #define SPEC(idx) ((s_pack[(idx) >> 3] >> (((idx) & 7) << 2)) & 0xFu)

    int v = tid;
    // Paired iterations: 6 independent LDG.128s issued up front.
    for (; v + stride < nvec; v += 2 * stride) {
        int v2 = v + stride;
        float4 ea = ldcs_f4(&eng4[v]);
        int4   ca = ldcs_i4(&c4[v]);
        int4   na = ldcs_i4(&n4[v]);
        float4 eb = ldcs_f4(&eng4[v2]);
        int4   cb = ldcs_i4(&c4[v2]);
        int4   nb = ldcs_i4(&n4[v2]);

        float a0 = ea.x * s_scale[(SPEC(ca.x) << 4) | SPEC(na.x)];
        float a1 = ea.y * s_scale[(SPEC(ca.y) << 4) | SPEC(na.y)];
        float a2 = ea.z * s_scale[(SPEC(ca.z) << 4) | SPEC(na.z)];
        float a3 = ea.w * s_scale[(SPEC(ca.w) << 4) | SPEC(na.w)];
        float b0 = eb.x * s_scale[(SPEC(cb.x) << 4) | SPEC(nb.x)];
        float b1 = eb.y * s_scale[(SPEC(cb.y) << 4) | SPEC(nb.y)];
        float b2 = eb.z * s_scale[(SPEC(cb.z) << 4) | SPEC(nb.z)];
        float b3 = eb.w * s_scale[(SPEC(cb.w) << 4) | SPEC(nb.w)];

        atomicAdd(&out[ca.x], a0);
        atomicAdd(&out[ca.y], a1);
        atomicAdd(&out[ca.z], a2);
        atomicAdd(&out[ca.w], a3);
        atomicAdd(&out[cb.x], b0);
        atomicAdd(&out[cb.y], b1);
        atomicAdd(&out[cb.z], b2);
        atomicAdd(&out[cb.w], b3);
    }
    // Possible single leftover vec4 for this thread.
    if (v < nvec) {
        float4 ea = ldcs_f4(&eng4[v]);
        int4   ca = ldcs_i4(&c4[v]);
        int4   na = ldcs_i4(&n4[v]);
        float a0 = ea.x * s_scale[(SPEC(ca.x) << 4) | SPEC(na.x)];
        float a1 = ea.y * s_scale[(SPEC(ca.y) << 4) | SPEC(na.y)];
        float a2 = ea.z * s_scale[(SPEC(ca.z) << 4) | SPEC(na.z)];
        float a3 = ea.w * s_scale[(SPEC(ca.w) << 4) | SPEC(na.w)];
        atomicAdd(&out[ca.x], a0);
        atomicAdd(&out[ca.y], a1);
        atomicAdd(&out[ca.z], a2);
        atomicAdd(&out[ca.w], a3);
    }

    // Scalar tail (E not divisible by 4)
    int base = nvec << 2;
    for (int i = base + tid; i < E; i += stride) {
        int cc = ei_center[i];
        int nn = ei_neighbor[i];
        float val = edge_eng[i] * s_scale[(SPEC(cc) << 4) | SPEC(nn)];
        atomicAdd(&out[cc], val);
    }
    #undef SPEC
}

extern "C" void kernel_launch(void* const* d_in, const int* in_sizes, int n_in,
                              void* d_out, int out_size) {
    const float* edge_eng = (const float*)d_in[0];  // [E,1]
    const float* scales   = (const float*)d_in[1];  // [16,16]
    const int*   edge_idx = (const int*)d_in[2];    // [2,E]
    const int*   species  = (const int*)d_in[3];    // [N]
    float* out = (float*)d_out;

    int E = in_sizes[0];
    int N = out_size;
    int nwords = (N + 7) >> 3;

    const int* ei_center   = edge_idx;
    const int* ei_neighbor = edge_idx + E;

    size_t smem_bytes = 256 * sizeof(float) + (size_t)nwords * sizeof(uint32_t);
    cudaFuncSetAttribute(edge_energy_sum_kernel,
                         cudaFuncAttributeMaxDynamicSharedMemorySize,
                         (int)smem_bytes);

    int prep_n = (N > nwords ? N : nwords);
    prep_kernel<<<(prep_n + 255) / 256, 256>>>(species, out, N, nwords);

    int threads = 512;
    int blocks = 148 * 4;
    int nvec = E >> 2;
    int need = (nvec + threads - 1) / threads;
    if (blocks > need) blocks = need > 0 ? need : 1;
    edge_energy_sum_kernel<<<blocks, threads, smem_bytes>>>(
        edge_eng, scales, ei_center, ei_neighbor, out, E, nwords);
}